// round 3
// baseline (speedup 1.0000x reference)
#include <cuda_runtime.h>

#define NROWS  32768      // B*Q*W = 16*8*256
#define DIM    256
#define KCODES 1024
#define NQV    8          // NQ stages

typedef unsigned long long u64;

// ---- scratch (static device globals: allocation-free rule) ----
__device__ float  g_res[NROWS * DIM];        // 32 MB residual
__device__ float  g_rnorm[NROWS];            // per-row ||residual||^2 (current stage)
__device__ float  g_cnorm[NQV * KCODES];     // per-code squared norms
__device__ int    g_idx[NROWS];              // argmin per row for current stage
__device__ double g_loss;                    // sum of squared new-residuals across stages

// ============================================================
// init: residual = z ; rnorm = ||z_row||^2 ; loss = 0
// grid: NROWS/4 blocks x 256 threads (4 rows/block, one float4/thread)
// ============================================================
__global__ void init_kernel(const float* __restrict__ z) {
    __shared__ float warpsum[8];
    int tid = threadIdx.x;
    int row = blockIdx.x * 4 + (tid >> 6);
    int d   = (tid & 63) << 2;
    size_t off = (size_t)row * DIM + d;

    float4 v = *(const float4*)&z[off];
    *(float4*)&g_res[off] = v;

    float ls = v.x * v.x + v.y * v.y + v.z * v.z + v.w * v.w;
    #pragma unroll
    for (int s = 16; s >= 1; s >>= 1) ls += __shfl_xor_sync(0xffffffffu, ls, s);
    if ((tid & 31) == 0) warpsum[tid >> 5] = ls;
    __syncthreads();
    if (tid < 4) g_rnorm[blockIdx.x * 4 + tid] = warpsum[2 * tid] + warpsum[2 * tid + 1];
    if (blockIdx.x == 0 && tid == 0) g_loss = 0.0;
}

// ============================================================
// cnorm: one warp per code, all NQ codebooks at once
// ============================================================
__global__ void cnorm_kernel(const float* __restrict__ cbs) {
    int gw   = (blockIdx.x * blockDim.x + threadIdx.x) >> 5;  // code id 0..8191
    int lane = threadIdx.x & 31;
    const float* c = cbs + (size_t)gw * DIM;
    float s = 0.f;
    #pragma unroll
    for (int d = lane; d < DIM; d += 32) { float v = c[d]; s += v * v; }
    #pragma unroll
    for (int sh = 16; sh >= 1; sh >>= 1) s += __shfl_xor_sync(0xffffffffu, s, sh);
    if (lane == 0) g_cnorm[gw] = s;
}

// ============================================================
// argmin GEMM with packed fma.rn.f32x2 (2 fp32 FMAs / instr, IEEE per half)
//   acc = dot(2*res_row, code_k) ; dist = (rnorm - acc) + cnorm
// Accumulators paired over adjacent ROWS (natural from LDS.128 of A tile).
// B tile stored DUPLICATED (b,b) per code with granule permutation so each
// warp LDS.128 hits consecutive 16B granules (conflict-free).
// ============================================================
#define BM  128
#define BN  128
#define BKD 8
#define TM  8
#define TN  8

__global__ __launch_bounds__(256, 2)
void argmin_kernel(const float* __restrict__ cb,      // stage codebook [K][D]
                   float* __restrict__ out_tok,       // d_out + NROWS*DIM
                   int stage)
{
    __shared__ float As[BKD][BM + 4];        // 2*residual, [d][row]
    __shared__ float Bs2[BKD][2 * BN + 8];   // duplicated codes, permuted granules

    const int tid = threadIdx.x;
    const int tx  = tid & 15;          // code-group 0..15 (8 codes each)
    const int ty  = tid >> 4;          // row-group  0..15 (8 rows each)
    const int rowBase = blockIdx.x * BM;

    const int lr = tid >> 1;           // 0..127 : row/code for loading
    const int lh = (tid & 1) * 4;      // 0 or 4 : d sub-offset

    // permuted dup-pair float offset for pair index p (0..127):
    //   g = p>>1 ; phys granule = (g&3)*16 + (g>>2) ; slot = p&1
    const int bg    = lr >> 1;
    const int boff  = (((bg & 3) << 4) + (bg >> 2)) * 4 + (lr & 1) * 2;

    const float* __restrict__ res   = g_res;
    const float* __restrict__ cnorm = g_cnorm + (size_t)stage * KCODES;

    float rn[TM];
    #pragma unroll
    for (int i = 0; i < TM; i++) rn[i] = g_rnorm[rowBase + ty * TM + i];

    float bestD[TM];
    int   bestI[TM];
    #pragma unroll
    for (int i = 0; i < TM; i++) { bestD[i] = 3.402823466e38f; bestI[i] = 0; }

    for (int cc = 0; cc < KCODES; cc += BN) {
        u64 acc2[TM / 2][TN];            // low half = row 2ip, high half = row 2ip+1
        #pragma unroll
        for (int ip = 0; ip < TM / 2; ip++)
            #pragma unroll
            for (int j = 0; j < TN; j++) acc2[ip][j] = 0ull;

        for (int dk = 0; dk < DIM; dk += BKD) {
            __syncthreads();
            float4 av = *(const float4*)&res[(size_t)(rowBase + lr) * DIM + dk + lh];
            float4 bv = *(const float4*)&cb [(size_t)(cc      + lr) * DIM + dk + lh];
            As[lh + 0][lr] = 2.0f * av.x; As[lh + 1][lr] = 2.0f * av.y;
            As[lh + 2][lr] = 2.0f * av.z; As[lh + 3][lr] = 2.0f * av.w;
            Bs2[lh + 0][boff] = bv.x; Bs2[lh + 0][boff + 1] = bv.x;
            Bs2[lh + 1][boff] = bv.y; Bs2[lh + 1][boff + 1] = bv.y;
            Bs2[lh + 2][boff] = bv.z; Bs2[lh + 2][boff + 1] = bv.z;
            Bs2[lh + 3][boff] = bv.w; Bs2[lh + 3][boff + 1] = bv.w;
            __syncthreads();

            #pragma unroll
            for (int d = 0; d < BKD; d++) {
                // A row-pairs: (a0,a1),(a2,a3),(a4,a5),(a6,a7)
                ulonglong2 av0 = *(const ulonglong2*)&As[d][ty * TM];
                ulonglong2 av1 = *(const ulonglong2*)&As[d][ty * TM + 4];
                u64 a2p[4] = { av0.x, av0.y, av1.x, av1.y };
                // B dup-pairs: load c -> pairs j=2c, 2c+1 (granule c*16+tx)
                u64 b2[TN];
                #pragma unroll
                for (int c = 0; c < 4; c++) {
                    ulonglong2 bvv = *(const ulonglong2*)&Bs2[d][(c * 16 + tx) * 4];
                    b2[2 * c]     = bvv.x;
                    b2[2 * c + 1] = bvv.y;
                }
                #pragma unroll
                for (int ip = 0; ip < TM / 2; ip++)
                    #pragma unroll
                    for (int j = 0; j < TN; j++)
                        asm("fma.rn.f32x2 %0, %1, %2, %0;"
                            : "+l"(acc2[ip][j]) : "l"(a2p[ip]), "l"(b2[j]));
            }
        }

        // dist = (rn - acc) + cn ; strict '<' + ascending code order = first-min
        #pragma unroll
        for (int j = 0; j < TN; j++) {
            int code = cc + tx * TN + j;
            float cn = __ldg(&cnorm[code]);
            #pragma unroll
            for (int ip = 0; ip < TM / 2; ip++) {
                u64 v = acc2[ip][j];
                float alo = __int_as_float((int)(v & 0xffffffffull));
                float ahi = __int_as_float((int)(v >> 32));
                int ilo = 2 * ip, ihi = 2 * ip + 1;
                float dlo = __fadd_rn(__fadd_rn(rn[ilo], -alo), cn);
                float dhi = __fadd_rn(__fadd_rn(rn[ihi], -ahi), cn);
                if (dlo < bestD[ilo]) { bestD[ilo] = dlo; bestI[ilo] = code; }
                if (dhi < bestD[ihi]) { bestD[ihi] = dhi; bestI[ihi] = code; }
            }
        }
    }

    // reduce across the 16 tx-threads sharing each row group (ties -> lower index)
    #pragma unroll
    for (int s = 8; s >= 1; s >>= 1) {
        #pragma unroll
        for (int i = 0; i < TM; i++) {
            float od = __shfl_xor_sync(0xffffffffu, bestD[i], s);
            int   oi = __shfl_xor_sync(0xffffffffu, bestI[i], s);
            if (od < bestD[i] || (od == bestD[i] && oi < bestI[i])) {
                bestD[i] = od; bestI[i] = oi;
            }
        }
    }

    if (tx == 0) {
        #pragma unroll
        for (int i = 0; i < TM; i++) {
            int row = rowBase + ty * TM + i;
            g_idx[row] = bestI[i];
            out_tok[(size_t)row * NQV + stage] = (float)bestI[i];
        }
    }
}

// ============================================================
// update: residual -= code ; rnorm = ||new residual||^2 ; loss += same
// (qtot no longer materialized: recovered as z - residual_final at the end)
// ============================================================
__global__ void update_kernel(const float* __restrict__ cb) {
    __shared__ float warpsum[8];
    int tid = threadIdx.x;
    int row = blockIdx.x * 4 + (tid >> 6);
    int d   = (tid & 63) << 2;
    int idx = g_idx[row];
    size_t off = (size_t)row * DIM + d;

    float4 c = *(const float4*)&cb[(size_t)idx * DIM + d];
    float4 r = *(const float4*)&g_res[off];
    float4 rv = make_float4(r.x - c.x, r.y - c.y, r.z - c.z, r.w - c.w);
    *(float4*)&g_res[off] = rv;

    float ls = rv.x * rv.x + rv.y * rv.y + rv.z * rv.z + rv.w * rv.w;
    #pragma unroll
    for (int s = 16; s >= 1; s >>= 1) ls += __shfl_xor_sync(0xffffffffu, ls, s);
    if ((tid & 31) == 0) warpsum[tid >> 5] = ls;
    __syncthreads();
    if (tid < 4) g_rnorm[blockIdx.x * 4 + tid] = warpsum[2 * tid] + warpsum[2 * tid + 1];
    if (tid == 0) {
        float t = 0.f;
        #pragma unroll
        for (int w = 0; w < 8; w++) t += warpsum[w];
        atomicAdd(&g_loss, (double)t);
    }
}

// ============================================================
// finalize: qtot = z - res_final ; out = z + (qtot - z) ; write closs scalar
// ============================================================
__global__ void finalize_kernel(const float* __restrict__ z, float* __restrict__ out) {
    int i = blockIdx.x * blockDim.x + threadIdx.x;   // over 2097152 float4
    float4 zv = ((const float4*)z)[i];
    float4 rv = ((const float4*)g_res)[i];
    float4 qv;
    qv.x = zv.x + ((zv.x - rv.x) - zv.x);
    qv.y = zv.y + ((zv.y - rv.y) - zv.y);
    qv.z = zv.z + ((zv.z - rv.z) - zv.z);
    qv.w = zv.w + ((zv.w - rv.w) - zv.w);
    ((float4*)out)[i] = qv;
    if (i == 0) {
        double closs = 1.25 * g_loss / ((double)NROWS * (double)DIM * (double)NQV);
        out[(size_t)NROWS * DIM + (size_t)NROWS * NQV] = (float)closs;
    }
}

// ============================================================
extern "C" void kernel_launch(void* const* d_in, const int* in_sizes, int n_in,
                              void* d_out, int out_size) {
    const float* z   = (const float*)d_in[0];   // [16,8,256,256] float32
    const float* cbs = (const float*)d_in[1];   // [8,1024,256]   float32
    float* out     = (float*)d_out;
    float* out_tok = out + (size_t)NROWS * DIM;

    init_kernel<<<NROWS / 4, 256>>>(z);
    cnorm_kernel<<<(NQV * KCODES * 32) / 256, 256>>>(cbs);

    for (int s = 0; s < NQV; s++) {
        const float* cb = cbs + (size_t)s * KCODES * DIM;
        argmin_kernel<<<NROWS / BM, 256>>>(cb, out_tok, s);
        update_kernel<<<NROWS / 4, 256>>>(cb);
    }

    finalize_kernel<<<(NROWS * DIM / 4) / 256, 256>>>(z, out);
}

// round 8
// speedup vs baseline: 2.1196x; 2.1196x over previous
#include <cuda_runtime.h>
#include <cuda_fp16.h>
#include <cstdint>

#define NROWS  32768      // B*Q*W
#define DIM    256
#define KCODES 1024
#define NQV    8
#define MARGIN 0.125f

// ---- scratch (device globals: allocation-free rule) ----
__device__ float  g_res[NROWS * DIM];          // fp32 residual
__device__ float  g_rnorm[NROWS];              // per-row ||res||^2
__device__ float  g_cnorm[NQV * KCODES];       // per-code ||c||^2
__device__ float  g_dist[NROWS * KCODES];      // coarse hm = cn - acc   (128 MB)
__device__ float  g_dmin[NROWS];               // per-row min of hm
__device__ double g_loss;
__device__ __half g_ah[NROWS * DIM];           // fl16(2*residual)
__device__ __half g_bh[NQV * KCODES * DIM];    // fl16(codebook)

__device__ __forceinline__ uint32_t smem_u32(const void* p) {
    uint32_t a;
    asm("{ .reg .u64 t; cvta.to.shared.u64 t, %1; cvt.u32.u64 %0, t; }" : "=r"(a) : "l"(p));
    return a;
}

// ============================================================
// init: residual = z ; rnorm ; g_ah = fl16(2z) ; loss = 0
// grid NROWS/4 x 256 (4 rows/block, float4/thread)
// ============================================================
__global__ void init_kernel(const float* __restrict__ z) {
    __shared__ float warpsum[8];
    int tid = threadIdx.x;
    int row = blockIdx.x * 4 + (tid >> 6);
    int d   = (tid & 63) << 2;
    size_t off = (size_t)row * DIM + d;

    float4 v = *(const float4*)&z[off];
    *(float4*)&g_res[off] = v;
    *(__half2*)&g_ah[off]     = __floats2half2_rn(2.f * v.x, 2.f * v.y);
    *(__half2*)&g_ah[off + 2] = __floats2half2_rn(2.f * v.z, 2.f * v.w);

    float ls = v.x * v.x + v.y * v.y + v.z * v.z + v.w * v.w;
    #pragma unroll
    for (int s = 16; s >= 1; s >>= 1) ls += __shfl_xor_sync(0xffffffffu, ls, s);
    if ((tid & 31) == 0) warpsum[tid >> 5] = ls;
    __syncthreads();
    if (tid < 4) g_rnorm[blockIdx.x * 4 + tid] = warpsum[2 * tid] + warpsum[2 * tid + 1];
    if (blockIdx.x == 0 && tid == 0) g_loss = 0.0;
}

// ============================================================
// cbprep: g_bh = fl16(cb)   (all stages)
// ============================================================
__global__ void cbprep_kernel(const float* __restrict__ cbs) {
    size_t i = (size_t)(blockIdx.x * blockDim.x + threadIdx.x) * 4;
    float4 c = *(const float4*)&cbs[i];
    *(__half2*)&g_bh[i]     = __floats2half2_rn(c.x, c.y);
    *(__half2*)&g_bh[i + 2] = __floats2half2_rn(c.z, c.w);
}

// ============================================================
// cnorm
// ============================================================
__global__ void cnorm_kernel(const float* __restrict__ cbs) {
    int gw   = (blockIdx.x * blockDim.x + threadIdx.x) >> 5;
    int lane = threadIdx.x & 31;
    const float* c = cbs + (size_t)gw * DIM;
    float s = 0.f;
    #pragma unroll
    for (int d = lane; d < DIM; d += 32) { float v = c[d]; s += v * v; }
    #pragma unroll
    for (int sh = 16; sh >= 1; sh >>= 1) s += __shfl_xor_sync(0xffffffffu, s, sh);
    if (lane == 0) g_cnorm[gw] = s;
}

// ============================================================
// coarse distance pass: mma.sync.m16n8k16 single fp16 pass
//   per CTA: 128 rows; 8 nc x 128 codes; 4 kc x 64 k
//   writes g_dist[row][code] = cn - acc, g_dmin[row]
// ============================================================
#define APITCH 264                 // halves per A row (256 + 8 pad)
#define ABYTES (128 * APITCH * 2)  // 67584
#define BPITCH 72
#define BTILE  (128 * BPITCH * 2)  // 18432
#define SMEM_TOTAL (ABYTES + 2 * BTILE)
#define NTILES 32                  // 8 nc * 4 kc

__device__ __forceinline__ void ldmatrix_x4(uint32_t& r0, uint32_t& r1, uint32_t& r2, uint32_t& r3, uint32_t addr) {
    asm volatile("ldmatrix.sync.aligned.m8n8.x4.shared.b16 {%0,%1,%2,%3}, [%4];"
                 : "=r"(r0), "=r"(r1), "=r"(r2), "=r"(r3) : "r"(addr));
}
__device__ __forceinline__ void mma16816(float* c, uint32_t a0, uint32_t a1, uint32_t a2, uint32_t a3,
                                         uint32_t b0, uint32_t b1) {
    asm volatile("mma.sync.aligned.m16n8k16.row.col.f32.f16.f16.f32 "
                 "{%0,%1,%2,%3}, {%4,%5,%6,%7}, {%8,%9}, {%0,%1,%2,%3};"
                 : "+f"(c[0]), "+f"(c[1]), "+f"(c[2]), "+f"(c[3])
                 : "r"(a0), "r"(a1), "r"(a2), "r"(a3), "r"(b0), "r"(b1));
}
#define CPASYNC16(s, g) asm volatile("cp.async.cg.shared.global [%0], [%1], 16;" :: "r"(s), "l"(g))

extern "C" __global__ void __launch_bounds__(256, 1)
coarse_kernel(int stage)
{
    extern __shared__ char sm[];
    const uint32_t smb = smem_u32(sm);
    const int tid  = threadIdx.x;
    const int wid  = tid >> 5;
    const int lane = tid & 31;
    const int rowBase = blockIdx.x * 128;

    // A tile: fl16(2*res), 128 rows x 256 halves
    {
        const __half* ap = g_ah + (size_t)rowBase * DIM;
        #pragma unroll
        for (int i = 0; i < 16; i++) {
            int idx = tid + i * 256;
            int r   = idx >> 5;
            int c8  = idx & 31;
            *(uint4*)(sm + (r * APITCH + c8 * 8) * 2) = *(const uint4*)(ap + (size_t)r * DIM + c8 * 8);
        }
    }
    __syncthreads();

    const float* __restrict__ cnorm = g_cnorm + (size_t)stage * KCODES;

    const int aRow   = wid * 16 + (lane & 7) + 8 * ((lane >> 3) & 1);
    const int aCol8  = (lane >> 4) * 8;
    const uint32_t aBase = smb + (aRow * APITCH + aCol8) * 2;
    const int bN     = (lane & 7) + 8 * ((lane >> 4) & 1);
    const int bK8    = 8 * ((lane >> 3) & 1);
    const uint32_t bFragBase = (uint32_t)((bN * BPITCH + bK8) * 2);

    const int ldRow = tid >> 3;
    const int ldSeg = tid & 7;

    const int rlo = rowBase + wid * 16 + (lane >> 2);
    const int rhi = rlo + 8;

    float bestDLo = 3.402823466e38f, bestDHi = 3.402823466e38f;

    float acc[16][4];
    #pragma unroll
    for (int nb = 0; nb < 16; nb++)
        #pragma unroll
        for (int q = 0; q < 4; q++) acc[nb][q] = 0.f;

    // prefetch tile 0 (nc0, kc0)
    {
        const __half* gb = g_bh + ((size_t)stage * KCODES) * DIM;
        #pragma unroll
        for (int i = 0; i < 4; i++) {
            int r = ldRow + i * 32;
            CPASYNC16(smb + ABYTES + (r * BPITCH + ldSeg * 8) * 2,
                      gb + (size_t)r * DIM + ldSeg * 8);
        }
        asm volatile("cp.async.commit_group;");
    }

    for (int tt = 0; tt < NTILES; tt++) {
        const int b = tt & 1;
        if (tt + 1 < NTILES) {
            int t2 = tt + 1;
            int nc2 = t2 >> 2, kc2 = t2 & 3;
            const __half* gb = g_bh + ((size_t)stage * KCODES + nc2 * 128) * DIM + kc2 * 64;
            uint32_t dstb = smb + ABYTES + (b ^ 1) * BTILE;
            #pragma unroll
            for (int i = 0; i < 4; i++) {
                int r = ldRow + i * 32;
                CPASYNC16(dstb + (r * BPITCH + ldSeg * 8) * 2,
                          gb + (size_t)r * DIM + ldSeg * 8);
            }
            asm volatile("cp.async.commit_group;");
            asm volatile("cp.async.wait_group 1;");
        } else {
            asm volatile("cp.async.wait_group 0;");
        }
        __syncthreads();

        const int kc = tt & 3;
        const uint32_t aTile = aBase + (kc * 64) * 2;
        const uint32_t bBuf  = smb + ABYTES + b * BTILE + bFragBase;

        #pragma unroll
        for (int ks = 0; ks < 4; ks++) {
            uint32_t a0, a1, a2, a3;
            ldmatrix_x4(a0, a1, a2, a3, aTile + ks * 32);
            #pragma unroll
            for (int nbp = 0; nbp < 8; nbp++) {
                uint32_t r0, r1, r2, r3;
                ldmatrix_x4(r0, r1, r2, r3, bBuf + (nbp * 16 * BPITCH + ks * 16) * 2);
                mma16816(acc[2 * nbp],     a0, a1, a2, a3, r0, r1);
                mma16816(acc[2 * nbp + 1], a0, a1, a2, a3, r2, r3);
            }
        }
        __syncthreads();

        if (kc == 3) {
            const int nc = tt >> 2;
            #pragma unroll
            for (int nb = 0; nb < 16; nb++) {
                int code0 = nc * 128 + nb * 8 + 2 * (lane & 3);
                float cn0 = __ldg(&cnorm[code0]);
                float cn1 = __ldg(&cnorm[code0 + 1]);
                float hL0 = cn0 - acc[nb][0];
                float hL1 = cn1 - acc[nb][1];
                float hH0 = cn0 - acc[nb][2];
                float hH1 = cn1 - acc[nb][3];
                *(float2*)&g_dist[(size_t)rlo * KCODES + code0] = make_float2(hL0, hL1);
                *(float2*)&g_dist[(size_t)rhi * KCODES + code0] = make_float2(hH0, hH1);
                bestDLo = fminf(bestDLo, fminf(hL0, hL1));
                bestDHi = fminf(bestDHi, fminf(hH0, hH1));
                acc[nb][0] = acc[nb][1] = acc[nb][2] = acc[nb][3] = 0.f;
            }
        }
    }

    // min over the 4 lanes sharing each row
    #pragma unroll
    for (int s = 1; s <= 2; s <<= 1) {
        bestDLo = fminf(bestDLo, __shfl_xor_sync(0xffffffffu, bestDLo, s));
        bestDHi = fminf(bestDHi, __shfl_xor_sync(0xffffffffu, bestDHi, s));
    }
    if ((lane & 3) == 0) {
        g_dmin[rlo] = bestDLo;
        g_dmin[rhi] = bestDHi;
    }
}

// ============================================================
// refine + update: one warp per row.
//   exact fp32 rescoring of all codes with hm <= dmin + MARGIN,
//   then residual -= code ; rnorm ; g_ah ; loss ; token write
// ============================================================
__global__ void __launch_bounds__(256, 4)
refine_update_kernel(const float* __restrict__ cb,     // stage codebook
                     float* __restrict__ out_tok, int stage)
{
    __shared__ float blksum[8];
    const int tid  = threadIdx.x;
    const int wib  = tid >> 5;                 // warp in block
    const int lane = tid & 31;
    const int row  = blockIdx.x * 8 + wib;

    const float* __restrict__ dr  = g_dist + (size_t)row * KCODES;
    const float* __restrict__ cnp = g_cnorm + (size_t)stage * KCODES;
    const float* __restrict__ res = g_res + (size_t)row * DIM;
    const float  rn = g_rnorm[row];
    const float  T  = g_dmin[row] + MARGIN;

    float bd = 3.402823466e38f;
    int   bi = 0x7fffffff;

    for (int i = 0; i < 32; i++) {
        int c = lane + i * 32;
        float hv = dr[c];
        if (hv <= T) {
            const float4* cp = (const float4*)(cb + (size_t)c * DIM);
            const float4* rp = (const float4*)res;
            float dot = 0.f;
            #pragma unroll 8
            for (int k = 0; k < 64; k++) {
                float4 cv = cp[k], rv = rp[k];
                dot = fmaf(2.f * rv.x, cv.x, dot);
                dot = fmaf(2.f * rv.y, cv.y, dot);
                dot = fmaf(2.f * rv.z, cv.z, dot);
                dot = fmaf(2.f * rv.w, cv.w, dot);
            }
            float dd = __fadd_rn(__fadd_rn(rn, -dot), __ldg(&cnp[c]));
            if (dd < bd || (dd == bd && c < bi)) { bd = dd; bi = c; }
        }
    }

    // warp argmin (ties -> lower index)
    #pragma unroll
    for (int s = 16; s >= 1; s >>= 1) {
        float od = __shfl_xor_sync(0xffffffffu, bd, s);
        int   oi = __shfl_xor_sync(0xffffffffu, bi, s);
        if (od < bd || (od == bd && oi < bi)) { bd = od; bi = oi; }
    }

    // ---- update: residual -= cb[bi] ; limbs ; rnorm ; loss ----
    const float4* cw = (const float4*)(cb + (size_t)bi * DIM);
    float lsum = 0.f;
    #pragma unroll
    for (int k = lane; k < 64; k += 32) {
        float4 rv = ((const float4*)res)[k];
        float4 cv = cw[k];
        rv.x -= cv.x; rv.y -= cv.y; rv.z -= cv.z; rv.w -= cv.w;
        ((float4*)(g_res + (size_t)row * DIM))[k] = rv;
        size_t off = (size_t)row * DIM + k * 4;
        *(__half2*)&g_ah[off]     = __floats2half2_rn(2.f * rv.x, 2.f * rv.y);
        *(__half2*)&g_ah[off + 2] = __floats2half2_rn(2.f * rv.z, 2.f * rv.w);
        lsum += rv.x * rv.x + rv.y * rv.y + rv.z * rv.z + rv.w * rv.w;
    }
    #pragma unroll
    for (int s = 16; s >= 1; s >>= 1) lsum += __shfl_xor_sync(0xffffffffu, lsum, s);

    if (lane == 0) {
        g_rnorm[row] = lsum;
        out_tok[(size_t)row * NQV + stage] = (float)bi;
        blksum[wib] = lsum;
    }
    __syncthreads();
    if (tid == 0) {
        float t = 0.f;
        #pragma unroll
        for (int w = 0; w < 8; w++) t += blksum[w];
        atomicAdd(&g_loss, (double)t);
    }
}

// ============================================================
// finalize: out = z + ((z - res) - z) ; closs scalar
// ============================================================
__global__ void finalize_kernel(const float* __restrict__ z, float* __restrict__ out) {
    int i = blockIdx.x * blockDim.x + threadIdx.x;
    float4 zv = ((const float4*)z)[i];
    float4 rv = ((const float4*)g_res)[i];
    float4 qv;
    qv.x = zv.x + ((zv.x - rv.x) - zv.x);
    qv.y = zv.y + ((zv.y - rv.y) - zv.y);
    qv.z = zv.z + ((zv.z - rv.z) - zv.z);
    qv.w = zv.w + ((zv.w - rv.w) - zv.w);
    ((float4*)out)[i] = qv;
    if (i == 0) {
        double closs = 1.25 * g_loss / ((double)NROWS * (double)DIM * (double)NQV);
        out[(size_t)NROWS * DIM + (size_t)NROWS * NQV] = (float)closs;
    }
}

// ============================================================
extern "C" void kernel_launch(void* const* d_in, const int* in_sizes, int n_in,
                              void* d_out, int out_size) {
    const float* z   = (const float*)d_in[0];   // [16,8,256,256] f32
    const float* cbs = (const float*)d_in[1];   // [8,1024,256]   f32
    float* out     = (float*)d_out;
    float* out_tok = out + (size_t)NROWS * DIM;

    cudaFuncSetAttribute(coarse_kernel, cudaFuncAttributeMaxDynamicSharedMemorySize, SMEM_TOTAL);

    init_kernel<<<NROWS / 4, 256>>>(z);
    cbprep_kernel<<<(NQV * KCODES * DIM / 4) / 256, 256>>>(cbs);
    cnorm_kernel<<<(NQV * KCODES * 32) / 256, 256>>>(cbs);

    for (int s = 0; s < NQV; s++) {
        const float* cb = cbs + (size_t)s * KCODES * DIM;
        coarse_kernel<<<NROWS / 128, 256, SMEM_TOTAL>>>(s);
        refine_update_kernel<<<NROWS / 8, 256>>>(cb, out_tok, s);
    }

    finalize_kernel<<<(NROWS * DIM / 4) / 256, 256>>>(z, out);
}

// round 9
// speedup vs baseline: 4.1936x; 1.9785x over previous
#include <cuda_runtime.h>
#include <cuda_fp16.h>
#include <cstdint>

#define NROWS  32768      // B*Q*W
#define DIM    256
#define KCODES 1024
#define NQV    8
#define MARGIN 0.125f

// ---- scratch (device globals: allocation-free rule) ----
__device__ float  g_res[NROWS * DIM];          // fp32 residual
__device__ float  g_rnorm[NROWS];              // per-row ||res||^2
__device__ float  g_cnorm[NQV * KCODES];       // per-code ||c||^2
__device__ double g_loss;
__device__ __half g_ah[NROWS * DIM];           // fl16(2*residual)
__device__ __half g_bh[NQV * KCODES * DIM];    // fl16(codebook)

__device__ __forceinline__ uint32_t smem_u32(const void* p) {
    uint32_t a;
    asm("{ .reg .u64 t; cvta.to.shared.u64 t, %1; cvt.u32.u64 %0, t; }" : "=r"(a) : "l"(p));
    return a;
}

// ============================================================
// init: residual = z ; rnorm ; g_ah = fl16(2z) ; loss = 0
// ============================================================
__global__ void init_kernel(const float* __restrict__ z) {
    __shared__ float warpsum[8];
    int tid = threadIdx.x;
    int row = blockIdx.x * 4 + (tid >> 6);
    int d   = (tid & 63) << 2;
    size_t off = (size_t)row * DIM + d;

    float4 v = *(const float4*)&z[off];
    *(float4*)&g_res[off] = v;
    *(__half2*)&g_ah[off]     = __floats2half2_rn(2.f * v.x, 2.f * v.y);
    *(__half2*)&g_ah[off + 2] = __floats2half2_rn(2.f * v.z, 2.f * v.w);

    float ls = v.x * v.x + v.y * v.y + v.z * v.z + v.w * v.w;
    #pragma unroll
    for (int s = 16; s >= 1; s >>= 1) ls += __shfl_xor_sync(0xffffffffu, ls, s);
    if ((tid & 31) == 0) warpsum[tid >> 5] = ls;
    __syncthreads();
    if (tid < 4) g_rnorm[blockIdx.x * 4 + tid] = warpsum[2 * tid] + warpsum[2 * tid + 1];
    if (blockIdx.x == 0 && tid == 0) g_loss = 0.0;
}

// ============================================================
// cbprep: g_bh = fl16(cb) for all stages
// ============================================================
__global__ void cbprep_kernel(const float* __restrict__ cbs) {
    size_t i = (size_t)(blockIdx.x * blockDim.x + threadIdx.x) * 4;
    float4 c = *(const float4*)&cbs[i];
    *(__half2*)&g_bh[i]     = __floats2half2_rn(c.x, c.y);
    *(__half2*)&g_bh[i + 2] = __floats2half2_rn(c.z, c.w);
}

// ============================================================
// cnorm
// ============================================================
__global__ void cnorm_kernel(const float* __restrict__ cbs) {
    int gw   = (blockIdx.x * blockDim.x + threadIdx.x) >> 5;
    int lane = threadIdx.x & 31;
    const float* c = cbs + (size_t)gw * DIM;
    float s = 0.f;
    #pragma unroll
    for (int d = lane; d < DIM; d += 32) { float v = c[d]; s += v * v; }
    #pragma unroll
    for (int sh = 16; sh >= 1; sh >>= 1) s += __shfl_xor_sync(0xffffffffu, s, sh);
    if (lane == 0) g_cnorm[gw] = s;
}

// ============================================================
// fused coarse(HMMA) + refine(exact fp32) + update, 64 rows/CTA
// ============================================================
#define RC      64
#define APITCH  264
#define ABYTES  (RC * APITCH * 2)     // 33792
#define BPITCH  72
#define BTILE   (128 * BPITCH * 2)    // 18432
#define DOFF    (ABYTES + 2 * BTILE)  // dist region offset
#define DPITCH  1032
#define DBYTES  (RC * DPITCH * 2)     // 132096
#define SMEM_TOTAL (DOFF + DBYTES)    // 202752
#define NTILES  32

__device__ __forceinline__ void ldmatrix_x4(uint32_t& r0, uint32_t& r1, uint32_t& r2, uint32_t& r3, uint32_t addr) {
    asm volatile("ldmatrix.sync.aligned.m8n8.x4.shared.b16 {%0,%1,%2,%3}, [%4];"
                 : "=r"(r0), "=r"(r1), "=r"(r2), "=r"(r3) : "r"(addr));
}
__device__ __forceinline__ void mma16816(float* c, uint32_t a0, uint32_t a1, uint32_t a2, uint32_t a3,
                                         uint32_t b0, uint32_t b1) {
    asm volatile("mma.sync.aligned.m16n8k16.row.col.f32.f16.f16.f32 "
                 "{%0,%1,%2,%3}, {%4,%5,%6,%7}, {%8,%9}, {%0,%1,%2,%3};"
                 : "+f"(c[0]), "+f"(c[1]), "+f"(c[2]), "+f"(c[3])
                 : "r"(a0), "r"(a1), "r"(a2), "r"(a3), "r"(b0), "r"(b1));
}
#define CPASYNC16(s, g) asm volatile("cp.async.cg.shared.global [%0], [%1], 16;" :: "r"(s), "l"(g))

extern "C" __global__ void __launch_bounds__(256, 1)
rvq_stage_kernel(const float* __restrict__ cb,
                 float* __restrict__ out_tok, int stage)
{
    extern __shared__ char sm[];
    const uint32_t smb = smem_u32(sm);
    const int tid  = threadIdx.x;
    const int wid  = tid >> 5;
    const int lane = tid & 31;
    const int rowBase = blockIdx.x * RC;

    const int wr = wid & 3;            // warp row-group (16 rows)
    const int wc = wid >> 2;           // warp code-half (64 of 128)

    // ---- A tile: fl16(2*res), 64 rows x 256 halves ----
    {
        const __half* ap = g_ah + (size_t)rowBase * DIM;
        #pragma unroll
        for (int i = 0; i < 8; i++) {
            int idx = tid + i * 256;
            int r   = idx >> 5;
            int c8  = idx & 31;
            *(uint4*)(sm + (r * APITCH + c8 * 8) * 2) = *(const uint4*)(ap + (size_t)r * DIM + c8 * 8);
        }
    }
    __syncthreads();

    const float* __restrict__ cnorm = g_cnorm + (size_t)stage * KCODES;

    const int aRow   = wr * 16 + (lane & 7) + 8 * ((lane >> 3) & 1);
    const int aCol8  = (lane >> 4) * 8;
    const uint32_t aBase = smb + (aRow * APITCH + aCol8) * 2;
    const int bN     = (lane & 7) + 8 * ((lane >> 4) & 1);
    const int bK8    = 8 * ((lane >> 3) & 1);
    const uint32_t bFragBase = (uint32_t)(((wc * 64 + bN) * BPITCH + bK8) * 2);

    const int ldRow = tid >> 3;
    const int ldSeg = tid & 7;

    float acc[8][4];
    #pragma unroll
    for (int nb = 0; nb < 8; nb++)
        #pragma unroll
        for (int q = 0; q < 4; q++) acc[nb][q] = 0.f;

    {
        const __half* gb = g_bh + ((size_t)stage * KCODES) * DIM;
        #pragma unroll
        for (int i = 0; i < 4; i++) {
            int r = ldRow + i * 32;
            CPASYNC16(smb + ABYTES + (r * BPITCH + ldSeg * 8) * 2,
                      gb + (size_t)r * DIM + ldSeg * 8);
        }
        asm volatile("cp.async.commit_group;");
    }

    for (int tt = 0; tt < NTILES; tt++) {
        const int b = tt & 1;
        if (tt + 1 < NTILES) {
            int t2 = tt + 1;
            int nc2 = t2 >> 2, kc2 = t2 & 3;
            const __half* gb = g_bh + ((size_t)stage * KCODES + nc2 * 128) * DIM + kc2 * 64;
            uint32_t dstb = smb + ABYTES + (b ^ 1) * BTILE;
            #pragma unroll
            for (int i = 0; i < 4; i++) {
                int r = ldRow + i * 32;
                CPASYNC16(dstb + (r * BPITCH + ldSeg * 8) * 2,
                          gb + (size_t)r * DIM + ldSeg * 8);
            }
            asm volatile("cp.async.commit_group;");
            asm volatile("cp.async.wait_group 1;");
        } else {
            asm volatile("cp.async.wait_group 0;");
        }
        __syncthreads();

        const int kc = tt & 3;
        const uint32_t aTile = aBase + (kc * 64) * 2;
        const uint32_t bBuf  = smb + ABYTES + b * BTILE + bFragBase;

        #pragma unroll
        for (int ks = 0; ks < 4; ks++) {
            uint32_t a0, a1, a2, a3;
            ldmatrix_x4(a0, a1, a2, a3, aTile + ks * 32);
            #pragma unroll
            for (int nbp = 0; nbp < 4; nbp++) {
                uint32_t r0, r1, r2, r3;
                ldmatrix_x4(r0, r1, r2, r3, bBuf + (nbp * 16 * BPITCH + ks * 16) * 2);
                mma16816(acc[2 * nbp],     a0, a1, a2, a3, r0, r1);
                mma16816(acc[2 * nbp + 1], a0, a1, a2, a3, r2, r3);
            }
        }
        __syncthreads();

        if (kc == 3) {   // epilogue: hm -> fp16 smem dist region
            const int nc = tt >> 2;
            const int rlo = wr * 16 + (lane >> 2);
            #pragma unroll
            for (int nb = 0; nb < 8; nb++) {
                int code0 = nc * 128 + wc * 64 + nb * 8 + 2 * (lane & 3);
                float cn0 = __ldg(&cnorm[code0]);
                float cn1 = __ldg(&cnorm[code0 + 1]);
                *(__half2*)(sm + DOFF + ((size_t)rlo * DPITCH + code0) * 2) =
                    __floats2half2_rn(cn0 - acc[nb][0], cn1 - acc[nb][1]);
                *(__half2*)(sm + DOFF + ((size_t)(rlo + 8) * DPITCH + code0) * 2) =
                    __floats2half2_rn(cn0 - acc[nb][2], cn1 - acc[nb][3]);
                acc[nb][0] = acc[nb][1] = acc[nb][2] = acc[nb][3] = 0.f;
            }
        }
    }
    __syncthreads();

    // ======== refine + update: 8 rows per warp ========
    float wloss = 0.f;
    for (int rr = 0; rr < 8; rr++) {
        const int row_l = wid * 8 + rr;
        const int row   = rowBase + row_l;
        const char* drow = sm + DOFF + (size_t)row_l * DPITCH * 2;

        float4 rA = ((const float4*)(g_res + (size_t)row * DIM))[lane * 2];
        float4 rB = ((const float4*)(g_res + (size_t)row * DIM))[lane * 2 + 1];
        const float rn = g_rnorm[row];

        float vmin = 3.402823466e38f;
        #pragma unroll
        for (int i = 0; i < 16; i++) {
            float2 f = __half22float2(*(const __half2*)(drow + (lane + 32 * i) * 4));
            vmin = fminf(vmin, fminf(f.x, f.y));
        }
        #pragma unroll
        for (int s = 16; s >= 1; s >>= 1) vmin = fminf(vmin, __shfl_xor_sync(0xffffffffu, vmin, s));
        const float T = vmin + MARGIN;

        float bd = 3.402823466e38f;
        int   bi = 0x7fffffff;
        #pragma unroll
        for (int i = 0; i < 16; i++) {
            float2 f = __half22float2(*(const __half2*)(drow + (lane + 32 * i) * 4));
            unsigned m0 = __ballot_sync(0xffffffffu, f.x <= T);
            unsigned m1 = __ballot_sync(0xffffffffu, f.y <= T);
            while (m0 | m1) {
                int c;
                if (m0) { int src = __ffs(m0) - 1; m0 &= m0 - 1; c = 2 * (src + 32 * i); }
                else    { int src = __ffs(m1) - 1; m1 &= m1 - 1; c = 2 * (src + 32 * i) + 1; }
                const float4* cp = (const float4*)(cb + (size_t)c * DIM);
                float4 c0 = cp[lane * 2], c1 = cp[lane * 2 + 1];
                float p = 0.f;
                p = fmaf(2.f * rA.x, c0.x, p); p = fmaf(2.f * rA.y, c0.y, p);
                p = fmaf(2.f * rA.z, c0.z, p); p = fmaf(2.f * rA.w, c0.w, p);
                p = fmaf(2.f * rB.x, c1.x, p); p = fmaf(2.f * rB.y, c1.y, p);
                p = fmaf(2.f * rB.z, c1.z, p); p = fmaf(2.f * rB.w, c1.w, p);
                #pragma unroll
                for (int s = 16; s >= 1; s >>= 1) p += __shfl_xor_sync(0xffffffffu, p, s);
                float dd = __fadd_rn(__fadd_rn(rn, -p), __ldg(&cnorm[c]));
                if (dd < bd || (dd == bd && c < bi)) { bd = dd; bi = c; }
            }
        }

        const float4* cw = (const float4*)(cb + (size_t)bi * DIM);
        float4 c0 = cw[lane * 2], c1 = cw[lane * 2 + 1];
        rA.x -= c0.x; rA.y -= c0.y; rA.z -= c0.z; rA.w -= c0.w;
        rB.x -= c1.x; rB.y -= c1.y; rB.z -= c1.z; rB.w -= c1.w;
        ((float4*)(g_res + (size_t)row * DIM))[lane * 2]     = rA;
        ((float4*)(g_res + (size_t)row * DIM))[lane * 2 + 1] = rB;
        size_t aoff = (size_t)row * DIM + lane * 8;
        *(__half2*)&g_ah[aoff]     = __floats2half2_rn(2.f * rA.x, 2.f * rA.y);
        *(__half2*)&g_ah[aoff + 2] = __floats2half2_rn(2.f * rA.z, 2.f * rA.w);
        *(__half2*)&g_ah[aoff + 4] = __floats2half2_rn(2.f * rB.x, 2.f * rB.y);
        *(__half2*)&g_ah[aoff + 6] = __floats2half2_rn(2.f * rB.z, 2.f * rB.w);

        float ls = rA.x * rA.x + rA.y * rA.y + rA.z * rA.z + rA.w * rA.w
                 + rB.x * rB.x + rB.y * rB.y + rB.z * rB.z + rB.w * rB.w;
        #pragma unroll
        for (int s = 16; s >= 1; s >>= 1) ls += __shfl_xor_sync(0xffffffffu, ls, s);
        if (lane == 0) {
            g_rnorm[row] = ls;
            out_tok[(size_t)row * NQV + stage] = (float)bi;
        }
        wloss += ls;
    }
    if (lane == 0) atomicAdd(&g_loss, (double)wloss);
}

// ============================================================
// finalize: out = z + ((z - res) - z) ; closs scalar
// ============================================================
__global__ void finalize_kernel(const float* __restrict__ z, float* __restrict__ out) {
    int i = blockIdx.x * blockDim.x + threadIdx.x;
    float4 zv = ((const float4*)z)[i];
    float4 rv = ((const float4*)g_res)[i];
    float4 qv;
    qv.x = zv.x + ((zv.x - rv.x) - zv.x);
    qv.y = zv.y + ((zv.y - rv.y) - zv.y);
    qv.z = zv.z + ((zv.z - rv.z) - zv.z);
    qv.w = zv.w + ((zv.w - rv.w) - zv.w);
    ((float4*)out)[i] = qv;
    if (i == 0) {
        double closs = 1.25 * g_loss / ((double)NROWS * (double)DIM * (double)NQV);
        out[(size_t)NROWS * DIM + (size_t)NROWS * NQV] = (float)closs;
    }
}

// ============================================================
extern "C" void kernel_launch(void* const* d_in, const int* in_sizes, int n_in,
                              void* d_out, int out_size) {
    const float* z   = (const float*)d_in[0];   // [16,8,256,256] f32
    const float* cbs = (const float*)d_in[1];   // [8,1024,256]   f32
    float* out     = (float*)d_out;
    float* out_tok = out + (size_t)NROWS * DIM;

    cudaFuncSetAttribute(rvq_stage_kernel, cudaFuncAttributeMaxDynamicSharedMemorySize, SMEM_TOTAL);

    init_kernel<<<NROWS / 4, 256>>>(z);
    cbprep_kernel<<<(NQV * KCODES * DIM / 4) / 256, 256>>>(cbs);
    cnorm_kernel<<<(NQV * KCODES * 32) / 256, 256>>>(cbs);

    for (int s = 0; s < NQV; s++) {
        const float* cb = cbs + (size_t)s * KCODES * DIM;
        rvq_stage_kernel<<<NROWS / RC, 256, SMEM_TOTAL>>>(cb, out_tok, s);
    }

    finalize_kernel<<<(NROWS * DIM / 4) / 256, 256>>>(z, out);
}